// round 7
// baseline (speedup 1.0000x reference)
#include <cuda_runtime.h>

// ConvGRU cell. O=8 output channels x P=4 pixels per thread, 128-thread
// blocks (128-pixel tile), __launch_bounds__(128,3) so 3 CTAs (12 warps,
// 3/SMSP) fit per SM -- the round-6 profile showed the port ratios are fine
// (LDC 50%, LDS 50%, issue 72%) but 2 warps/SMSP could not cover LDC/LDS
// latency. Weights in __constant__ (warp-uniform LDC.128), inputs staged in
// smem [c][px].

#define HW 65536        // 256*256
#define NB 8

typedef unsigned long long ull;

// [m][c][o] transposed weights (7*1024 floats) + 4 combined bias vectors.
__constant__ __align__(16) float cAll[7 * 1024 + 4 * 32];
__device__   __align__(16) float g_stage[7 * 1024 + 4 * 32];

__device__ __forceinline__ ull pack2(float a, float b) {
    ull r;
    asm("mov.b64 %0, {%1, %2};" : "=l"(r) : "f"(a), "f"(b));
    return r;
}
__device__ __forceinline__ void unpack2(ull v, float& a, float& b) {
    asm("mov.b64 {%0, %1}, %2;" : "=f"(a), "=f"(b) : "l"(v));
}
__device__ __forceinline__ void ffma2(ull& d, ull a, ull b) {
    asm("fma.rn.f32x2 %0, %1, %2, %3;" : "=l"(d) : "l"(a), "l"(b), "l"(d));
}
__device__ __forceinline__ float sigmoidf_(float a) {
    a = fminf(fmaxf(a, -30.f), 30.f);
    float e = __expf(-a);
    return __fdividef(1.f, 1.f + e);
}
__device__ __forceinline__ float tanhf_(float a) {
    a = fminf(fmaxf(a, -15.f), 15.f);
    float e = __expf(-2.f * a);
    return (1.f - e) * __fdividef(1.f, 1.f + e);
}

__global__ void prep_kernel(
    const float* __restrict__ w_xz, const float* __restrict__ w_hz,
    const float* __restrict__ w_xr, const float* __restrict__ w_hr,
    const float* __restrict__ w_c,  const float* __restrict__ w_u,
    const float* __restrict__ w_o,
    const float* __restrict__ b_xz, const float* __restrict__ b_hz,
    const float* __restrict__ b_xr, const float* __restrict__ b_hr,
    const float* __restrict__ b_c,  const float* __restrict__ b_u,
    const float* __restrict__ b_o)
{
    int t = threadIdx.x;               // 1024 threads
    int o = t & 31, c = t >> 5;
    g_stage[0 * 1024 + c * 32 + o] = w_xz[o * 32 + c];
    g_stage[1 * 1024 + c * 32 + o] = w_hz[o * 32 + c];
    g_stage[2 * 1024 + c * 32 + o] = w_xr[o * 32 + c];
    g_stage[3 * 1024 + c * 32 + o] = w_hr[o * 32 + c];
    g_stage[4 * 1024 + c * 32 + o] = w_c [o * 32 + c];
    g_stage[5 * 1024 + c * 32 + o] = w_u [o * 32 + c];
    g_stage[6 * 1024 + c * 32 + o] = w_o [o * 32 + c];
    if (t < 32) {
        g_stage[7168 +  0 + t] = b_xz[t] + b_hz[t];   // bz
        g_stage[7168 + 32 + t] = b_xr[t] + b_hr[t];   // br
        g_stage[7168 + 64 + t] = b_c[t]  + b_u[t];    // bc
        g_stage[7168 + 96 + t] = b_o[t];              // by
    }
}

__global__ void __launch_bounds__(128, 3) gru_fused_kernel(
    const float* __restrict__ x, const float* __restrict__ h,
    float* __restrict__ out)
{
    extern __shared__ float smem[];
    float* xs = smem;               // [32][128]
    float* hs = smem + 4096;        // [32][128]
    float* ts = smem + 8192;        // [32][128]  rv, then ht

    const int tid = threadIdx.x;
    const int pg  = tid & 31;           // pixel quad index (4 px)
    const int o0  = (tid >> 5) * 8;     // base output channel (warp-uniform)

    const int gp0 = blockIdx.x * 128;   // 4096 blocks cover 524288 px
    const int b   = gp0 >> 16;
    const int p0  = gp0 & 65535;

    // ---- stage input tiles xs/hs[c][px]: 1024 float4 per tensor ----
    {
        const float4* x4 = (const float4*)(x + (b * 32) * HW + p0);
        const float4* h4 = (const float4*)(h + (b * 32) * HW + p0);
#pragma unroll
        for (int k = 0; k < 8; k++) {
            int idx = tid + k * 128;        // 0..1023
            int c = idx >> 5, j = idx & 31;
            ((float4*)&xs[c * 128])[j] = x4[c * (HW / 4) + j];
            ((float4*)&hs[c * 128])[j] = h4[c * (HW / 4) + j];
        }
    }
    __syncthreads();

// one 2-matrix accumulation step at channel c into acc[4][4]
// acc[op][px]: f32x2 over output pair (o0+2op, o0+2op+1), pixel px of quad.
#define STEP2(acc, m1, in1, m2, in2, c)                                       \
    {                                                                         \
        float4 u = ((const float4*)&(in1)[(c) * 128])[pg];                    \
        float4 v = ((const float4*)&(in2)[(c) * 128])[pg];                    \
        ull du[4] = { pack2(u.x, u.x), pack2(u.y, u.y),                       \
                      pack2(u.z, u.z), pack2(u.w, u.w) };                     \
        ull dv[4] = { pack2(v.x, v.x), pack2(v.y, v.y),                       \
                      pack2(v.z, v.z), pack2(v.w, v.w) };                     \
        const ulonglong2* wa =                                                \
            (const ulonglong2*)&cAll[(m1) * 1024 + (c) * 32 + o0];            \
        const ulonglong2* wb =                                                \
            (const ulonglong2*)&cAll[(m2) * 1024 + (c) * 32 + o0];            \
        ulonglong2 wa0 = wa[0], wa1 = wa[1];                                  \
        ulonglong2 wb0 = wb[0], wb1 = wb[1];                                  \
        _Pragma("unroll")                                                     \
        for (int px = 0; px < 4; px++) {                                      \
            ffma2((acc)[0][px], wa0.x, du[px]);                               \
            ffma2((acc)[1][px], wa0.y, du[px]);                               \
            ffma2((acc)[2][px], wa1.x, du[px]);                               \
            ffma2((acc)[3][px], wa1.y, du[px]);                               \
            ffma2((acc)[0][px], wb0.x, dv[px]);                               \
            ffma2((acc)[1][px], wb0.y, dv[px]);                               \
            ffma2((acc)[2][px], wb1.x, dv[px]);                               \
            ffma2((acc)[3][px], wb1.y, dv[px]);                               \
        }                                                                     \
    }

#define STEP1(acc, m1, in1, c)                                                \
    {                                                                         \
        float4 u = ((const float4*)&(in1)[(c) * 128])[pg];                    \
        ull du[4] = { pack2(u.x, u.x), pack2(u.y, u.y),                       \
                      pack2(u.z, u.z), pack2(u.w, u.w) };                     \
        const ulonglong2* wa =                                                \
            (const ulonglong2*)&cAll[(m1) * 1024 + (c) * 32 + o0];            \
        ulonglong2 wa0 = wa[0], wa1 = wa[1];                                  \
        _Pragma("unroll")                                                     \
        for (int px = 0; px < 4; px++) {                                      \
            ffma2((acc)[0][px], wa0.x, du[px]);                               \
            ffma2((acc)[1][px], wa0.y, du[px]);                               \
            ffma2((acc)[2][px], wa1.x, du[px]);                               \
            ffma2((acc)[3][px], wa1.y, du[px]);                               \
        }                                                                     \
    }

#define INIT_ACC(acc, boff)                                                   \
    _Pragma("unroll")                                                         \
    for (int op = 0; op < 4; op++) {                                          \
        ull bb = pack2(cAll[7168 + (boff) + o0 + 2 * op],                     \
                       cAll[7168 + (boff) + o0 + 2 * op + 1]);                \
        _Pragma("unroll")                                                     \
        for (int px = 0; px < 4; px++) (acc)[op][px] = bb;                    \
    }

    // ---- r gate: racc = Wxr*x + Whr*h + br ----
    ull racc[4][4];
    INIT_ACC(racc, 32)
#pragma unroll
    for (int c = 0; c < 32; c++) STEP2(racc, 2, xs, 3, hs, c)

    // rv = sigmoid(r) * h -> ts
#pragma unroll
    for (int op = 0; op < 4; op++) {
        int oc0 = o0 + 2 * op, oc1 = oc0 + 1;
        float4 h0 = ((const float4*)&hs[oc0 * 128])[pg];
        float4 h1 = ((const float4*)&hs[oc1 * 128])[pg];
        const float* h0f = (const float*)&h0;
        const float* h1f = (const float*)&h1;
        float r0[4], r1[4];
#pragma unroll
        for (int px = 0; px < 4; px++) {
            float a0, a1;
            unpack2(racc[op][px], a0, a1);
            r0[px] = sigmoidf_(a0) * h0f[px];
            r1[px] = sigmoidf_(a1) * h1f[px];
        }
        ((float4*)&ts[oc0 * 128])[pg] = make_float4(r0[0], r0[1], r0[2], r0[3]);
        ((float4*)&ts[oc1 * 128])[pg] = make_float4(r1[0], r1[1], r1[2], r1[3]);
    }
    __syncthreads();

    // ---- candidate: cacc = Wc*x + Wu*rv + bc ----
    ull cacc[4][4];
    INIT_ACC(cacc, 64)
#pragma unroll
    for (int c = 0; c < 32; c++) STEP2(cacc, 4, xs, 5, ts, c)

    // ---- z gate: zacc = Wxz*x + Whz*h + bz ----
    ull zacc[4][4];
    INIT_ACC(zacc, 0)
#pragma unroll
    for (int c = 0; c < 32; c++) STEP2(zacc, 0, xs, 1, hs, c)
    __syncthreads();    // all warps done reading ts=rv

    // ---- blend: ht = h + sigmoid(z)*(tanh(c) - h) -> ts + gmem ----
    float* houtb = out + NB * 32 * HW + (b * 32) * HW + p0;
#pragma unroll
    for (int op = 0; op < 4; op++) {
        int oc0 = o0 + 2 * op, oc1 = oc0 + 1;
        float4 h0 = ((const float4*)&hs[oc0 * 128])[pg];
        float4 h1 = ((const float4*)&hs[oc1 * 128])[pg];
        const float* h0f = (const float*)&h0;
        const float* h1f = (const float*)&h1;
        float t0[4], t1[4];
#pragma unroll
        for (int px = 0; px < 4; px++) {
            float c0, c1, z0, z1;
            unpack2(cacc[op][px], c0, c1);
            unpack2(zacc[op][px], z0, z1);
            t0[px] = fmaf(sigmoidf_(z0), tanhf_(c0) - h0f[px], h0f[px]);
            t1[px] = fmaf(sigmoidf_(z1), tanhf_(c1) - h1f[px], h1f[px]);
        }
        float4 v0 = make_float4(t0[0], t0[1], t0[2], t0[3]);
        float4 v1 = make_float4(t1[0], t1[1], t1[2], t1[3]);
        ((float4*)&ts[oc0 * 128])[pg] = v0;
        ((float4*)&ts[oc1 * 128])[pg] = v1;
        ((float4*)(houtb + oc0 * HW))[pg] = v0;
        ((float4*)(houtb + oc1 * HW))[pg] = v1;
    }
    __syncthreads();

    // ---- output projection: y = Wo*ht + by ----
    ull yacc[4][4];
    INIT_ACC(yacc, 96)
#pragma unroll
    for (int c = 0; c < 32; c++) STEP1(yacc, 6, ts, c)

    float* youtb = out + (b * 32) * HW + p0;
#pragma unroll
    for (int op = 0; op < 4; op++) {
        int oc0 = o0 + 2 * op, oc1 = oc0 + 1;
        float y0[4], y1[4];
#pragma unroll
        for (int px = 0; px < 4; px++) unpack2(yacc[op][px], y0[px], y1[px]);
        ((float4*)(youtb + oc0 * HW))[pg] = make_float4(y0[0], y0[1], y0[2], y0[3]);
        ((float4*)(youtb + oc1 * HW))[pg] = make_float4(y1[0], y1[1], y1[2], y1[3]);
    }
}

extern "C" void kernel_launch(void* const* d_in, const int* in_sizes, int n_in,
                              void* d_out, int out_size) {
    const float* x    = (const float*)d_in[0];
    const float* h    = (const float*)d_in[1];
    const float* w_xz = (const float*)d_in[2];
    const float* b_xz = (const float*)d_in[3];
    const float* w_hz = (const float*)d_in[4];
    const float* b_hz = (const float*)d_in[5];
    const float* w_xr = (const float*)d_in[6];
    const float* b_xr = (const float*)d_in[7];
    const float* w_hr = (const float*)d_in[8];
    const float* b_hr = (const float*)d_in[9];
    const float* w_c  = (const float*)d_in[10];
    const float* b_c  = (const float*)d_in[11];
    const float* w_u  = (const float*)d_in[12];
    const float* b_u  = (const float*)d_in[13];
    const float* w_o  = (const float*)d_in[14];
    const float* b_o  = (const float*)d_in[15];
    float* out = (float*)d_out;

    prep_kernel<<<1, 1024>>>(w_xz, w_hz, w_xr, w_hr, w_c, w_u, w_o,
                             b_xz, b_hz, b_xr, b_hr, b_c, b_u, b_o);

    void *csym = nullptr, *gsym = nullptr;
    cudaGetSymbolAddress(&csym, cAll);
    cudaGetSymbolAddress(&gsym, g_stage);
    cudaMemcpyAsync(csym, gsym, sizeof(float) * (7 * 1024 + 4 * 32),
                    cudaMemcpyDeviceToDevice);

    cudaFuncSetAttribute(gru_fused_kernel,
                         cudaFuncAttributeMaxDynamicSharedMemorySize, 49152);
    gru_fused_kernel<<<4096, 128, 49152>>>(x, h, out);
}

// round 9
// speedup vs baseline: 3.0533x; 3.0533x over previous
#include <cuda_runtime.h>
#include <cuda_bf16.h>
#include <cstdint>

// ConvGRU cell via warp-level mma.sync (HMMA bf16, f32 accum) — baseline PTX,
// works at compute_103 (tcgen05 needs the sm_103a feature target the harness
// does not use). fp32 accuracy via bf16 hi/lo split (3 terms).
//
// Block = 128 threads = 4 warps; warp w owns pixels [32w,32w+32): every smem
// tile row is produced and consumed by the same warp -> no __syncthreads in
// the main pipeline, only __syncwarp.

#define HW 65536        // 256*256
#define NB 8

// ---- smem layout (dynamic) ----
// wf  : 7168 u32 B-fragments (28672 B)
// xs  : [128][72] bf16 (hi cols 0..31, lo 32..63, pad)  18432 B
// hs  : same
// ts  : same (rv then ht)
// stg : [128][33] f32 staging for coalesced gmem stores  16896 B
#define WF_BYTES   28672
#define TILE_BYTES 18432
#define SMEM_TOTAL (WF_BYTES + 3 * TILE_BYTES + 16896)

__device__ __align__(16) uint32_t g_wfrag[7168];
__device__ float g_bias_stage[128];
__constant__ float cBias[128];   // [bz | br | bc | by]

__device__ __forceinline__ float sigmoidf_(float a) {
    a = fminf(fmaxf(a, -30.f), 30.f);
    float e = __expf(-a);
    return __fdividef(1.f, 1.f + e);
}
__device__ __forceinline__ float tanhf_(float a) {
    a = fminf(fmaxf(a, -15.f), 15.f);
    float e = __expf(-2.f * a);
    return (1.f - e) * __fdividef(1.f, 1.f + e);
}
__device__ __forceinline__ void split2(float a, float b, uint32_t& hi, uint32_t& lo) {
    __nv_bfloat16 ha = __float2bfloat16(a);
    __nv_bfloat16 hb = __float2bfloat16(b);
    __nv_bfloat16 la = __float2bfloat16(a - __bfloat162float(ha));
    __nv_bfloat16 lb = __float2bfloat16(b - __bfloat162float(hb));
    hi = (uint32_t)__bfloat16_as_ushort(ha) | ((uint32_t)__bfloat16_as_ushort(hb) << 16);
    lo = (uint32_t)__bfloat16_as_ushort(la) | ((uint32_t)__bfloat16_as_ushort(lb) << 16);
}
__device__ __forceinline__ float bf_lo(uint32_t v) {
    return __bfloat162float(__ushort_as_bfloat16((unsigned short)(v & 0xFFFF)));
}
__device__ __forceinline__ float bf_hi(uint32_t v) {
    return __bfloat162float(__ushort_as_bfloat16((unsigned short)(v >> 16)));
}
__device__ __forceinline__ uint32_t smem_u32(const void* p) {
    uint32_t a;
    asm("{ .reg .u64 t; cvta.to.shared.u64 t, %1; cvt.u32.u64 %0, t; }"
        : "=r"(a) : "l"(p));
    return a;
}
__device__ __forceinline__ void ldmA(uint32_t a[4], uint32_t addr) {
    asm volatile("ldmatrix.sync.aligned.m8n8.x4.shared.b16 {%0,%1,%2,%3}, [%4];"
                 : "=r"(a[0]), "=r"(a[1]), "=r"(a[2]), "=r"(a[3]) : "r"(addr));
}
__device__ __forceinline__ void mma16816(float d[4], const uint32_t a[4],
                                         uint32_t b0, uint32_t b1) {
    asm volatile(
        "mma.sync.aligned.m16n8k16.row.col.f32.bf16.bf16.f32 "
        "{%0,%1,%2,%3}, {%4,%5,%6,%7}, {%8,%9}, {%0,%1,%2,%3};"
        : "+f"(d[0]), "+f"(d[1]), "+f"(d[2]), "+f"(d[3])
        : "r"(a[0]), "r"(a[1]), "r"(a[2]), "r"(a[3]), "r"(b0), "r"(b1));
}

// prep: build per-thread B fragments for m16n8k16 (b0={W[n][k],W[n][k+1]},
// b1 same at k+8), hi (term 0) and lo (term 1) parts. 7 blocks x 1024 thr.
__global__ void prep_kernel(
    const float* __restrict__ w_xz, const float* __restrict__ w_hz,
    const float* __restrict__ w_xr, const float* __restrict__ w_hr,
    const float* __restrict__ w_c,  const float* __restrict__ w_u,
    const float* __restrict__ w_o,
    const float* __restrict__ b_xz, const float* __restrict__ b_hz,
    const float* __restrict__ b_xr, const float* __restrict__ b_hr,
    const float* __restrict__ b_c,  const float* __restrict__ b_u,
    const float* __restrict__ b_o)
{
    int m = blockIdx.x;                  // 0..6
    int t = threadIdx.x;                 // 0..1023
    int lane = t & 31;
    int reg  = (t >> 5) & 1;
    int nt   = (t >> 6) & 3;
    int kt   = (t >> 8) & 1;
    int term = (t >> 9) & 1;
    int g = lane >> 2, tig = lane & 3;
    const float* Wm = (m == 0) ? w_xz : (m == 1) ? w_hz : (m == 2) ? w_xr :
                      (m == 3) ? w_hr : (m == 4) ? w_c  : (m == 5) ? w_u : w_o;
    int n  = nt * 8 + g;
    int kk = kt * 16 + 2 * tig + reg * 8;
    float w0 = Wm[n * 32 + kk];
    float w1 = Wm[n * 32 + kk + 1];
    __nv_bfloat16 h0 = __float2bfloat16(w0);
    __nv_bfloat16 h1 = __float2bfloat16(w1);
    uint32_t val;
    if (term == 0) {
        val = (uint32_t)__bfloat16_as_ushort(h0) |
              ((uint32_t)__bfloat16_as_ushort(h1) << 16);
    } else {
        __nv_bfloat16 l0 = __float2bfloat16(w0 - __bfloat162float(h0));
        __nv_bfloat16 l1 = __float2bfloat16(w1 - __bfloat162float(h1));
        val = (uint32_t)__bfloat16_as_ushort(l0) |
              ((uint32_t)__bfloat16_as_ushort(l1) << 16);
    }
    g_wfrag[((((m * 2 + term) * 2 + kt) * 4 + nt) * 2 + reg) * 32 + lane] = val;
    if (m == 0 && t < 32) {
        g_bias_stage[ 0 + t] = b_xz[t] + b_hz[t];
        g_bias_stage[32 + t] = b_xr[t] + b_hr[t];
        g_bias_stage[64 + t] = b_c[t]  + b_u[t];
        g_bias_stage[96 + t] = b_o[t];
    }
}

// D[2mt][4nt][4] += [Ah|Al|Ah] @ [Wh|Wh|Wl]^T for matrix m, A tile at abase.
__device__ __forceinline__ void gemm_tile(float d[2][4][4], uint32_t abase,
                                          int m, const uint32_t* wf,
                                          int lane, int wpx) {
    const int l15 = lane & 15, lhi = lane >> 4;
#pragma unroll
    for (int kt = 0; kt < 2; kt++) {
        uint32_t ah[2][4], al[2][4];
#pragma unroll
        for (int mt = 0; mt < 2; mt++) {
            uint32_t rowb = abase + (uint32_t)((wpx + mt * 16 + l15) * 144);
            uint32_t ca = (uint32_t)((kt * 16 + lhi * 8) * 2);
            ldmA(ah[mt], rowb + ca);
            ldmA(al[mt], rowb + ca + 64);
        }
        const uint32_t* bh = wf + (((m * 2 + 0) * 2 + kt) * 4) * 2 * 32;
        const uint32_t* bl = wf + (((m * 2 + 1) * 2 + kt) * 4) * 2 * 32;
#pragma unroll
        for (int nt = 0; nt < 4; nt++) {
            uint32_t bh0 = bh[(nt * 2 + 0) * 32 + lane];
            uint32_t bh1 = bh[(nt * 2 + 1) * 32 + lane];
            uint32_t bl0 = bl[(nt * 2 + 0) * 32 + lane];
            uint32_t bl1 = bl[(nt * 2 + 1) * 32 + lane];
            mma16816(d[0][nt], ah[0], bh0, bh1);
            mma16816(d[1][nt], ah[1], bh0, bh1);
            mma16816(d[0][nt], al[0], bh0, bh1);
            mma16816(d[1][nt], al[1], bh0, bh1);
            mma16816(d[0][nt], ah[0], bl0, bl1);
            mma16816(d[1][nt], ah[1], bl0, bl1);
        }
    }
}

__global__ void __launch_bounds__(128) gru_mma_kernel(
    const float* __restrict__ x, const float* __restrict__ h,
    float* __restrict__ out)
{
    extern __shared__ __align__(16) unsigned char dsm[];
    uint32_t* wf = (uint32_t*)dsm;
    uint32_t* xs = (uint32_t*)(dsm + WF_BYTES);               // u32 view, 36/row
    uint32_t* hs = (uint32_t*)(dsm + WF_BYTES + TILE_BYTES);
    uint32_t* ts = (uint32_t*)(dsm + WF_BYTES + 2 * TILE_BYTES);
    float*   stg = (float*)(dsm + WF_BYTES + 3 * TILE_BYTES);

    const int tid = threadIdx.x;
    const int wid = tid >> 5, lane = tid & 31;
    const int g = lane >> 2, tig = lane & 3;
    const int wpx = wid * 32;

    const uint32_t xs_a = smem_u32(xs);
    const uint32_t hs_a = smem_u32(hs);
    const uint32_t ts_a = smem_u32(ts);

    // ---- copy B fragments (coalesced, 1792 uint4) ----
    {
        const uint4* src = (const uint4*)g_wfrag;
        uint4* dst = (uint4*)wf;
#pragma unroll
        for (int k = 0; k < 14; k++) dst[tid + k * 128] = src[tid + k * 128];
    }

    const int gp0 = blockIdx.x * 128;   // 4096 blocks cover 524288 px
    const int b   = gp0 >> 16;
    const int p0  = gp0 & 65535;
    const float* xb = x + (b * 32) * HW + p0 + tid;
    const float* hb = h + (b * 32) * HW + p0 + tid;

    // ---- load x,h (coalesced), split, store tiles (row = own pixel) ----
#pragma unroll
    for (int j = 0; j < 16; j++) {
        float a0 = xb[(2 * j) * HW], a1 = xb[(2 * j + 1) * HW];
        float c0 = hb[(2 * j) * HW], c1 = hb[(2 * j + 1) * HW];
        uint32_t phi, plo;
        split2(a0, a1, phi, plo);
        xs[tid * 36 + j] = phi;  xs[tid * 36 + 16 + j] = plo;
        split2(c0, c1, phi, plo);
        hs[tid * 36 + j] = phi;  hs[tid * 36 + 16 + j] = plo;
    }
    __syncthreads();   // wf visible to all; tiles are warp-local anyway

    // ---- phase 1: z and r ----
    float dz[2][4][4] = {}, dr[2][4][4] = {};
    gemm_tile(dz, xs_a, 0, wf, lane, wpx);
    gemm_tile(dz, hs_a, 1, wf, lane, wpx);
    gemm_tile(dr, xs_a, 2, wf, lane, wpx);
    gemm_tile(dr, hs_a, 3, wf, lane, wpx);

    // z = sigmoid(z_pre + bz) kept in dz; rv = sigmoid(r_pre + br) * h -> ts
#pragma unroll
    for (int mt = 0; mt < 2; mt++)
#pragma unroll
        for (int nt = 0; nt < 4; nt++) {
            const int ch0 = nt * 8 + 2 * tig;
            const float bz0 = cBias[ch0], bz1 = cBias[ch0 + 1];
            const float br0 = cBias[32 + ch0], br1 = cBias[32 + ch0 + 1];
#pragma unroll
            for (int hf = 0; hf < 2; hf++) {
                int px = wpx + mt * 16 + g + hf * 8;
                int wb = px * 36 + nt * 4 + tig;
                uint32_t hh = hs[wb], hl = hs[wb + 16];
                float h0 = bf_lo(hh) + bf_lo(hl);
                float h1 = bf_hi(hh) + bf_hi(hl);
                dz[mt][nt][hf * 2 + 0] = sigmoidf_(dz[mt][nt][hf * 2 + 0] + bz0);
                dz[mt][nt][hf * 2 + 1] = sigmoidf_(dz[mt][nt][hf * 2 + 1] + bz1);
                float r0 = sigmoidf_(dr[mt][nt][hf * 2 + 0] + br0) * h0;
                float r1 = sigmoidf_(dr[mt][nt][hf * 2 + 1] + br1) * h1;
                uint32_t phi, plo;
                split2(r0, r1, phi, plo);
                ts[wb] = phi;  ts[wb + 16] = plo;
            }
        }
    __syncwarp();

    // ---- phase 2: candidate ----
    float dc[2][4][4] = {};
    gemm_tile(dc, xs_a, 4, wf, lane, wpx);
    gemm_tile(dc, ts_a, 5, wf, lane, wpx);
    __syncwarp();   // ts reads (ldmatrix) complete before overwrite below

    // blend: h_t = h + z*(tanh(c_pre+bc) - h) -> stg (f32) + ts (bf16 split)
#pragma unroll
    for (int mt = 0; mt < 2; mt++)
#pragma unroll
        for (int nt = 0; nt < 4; nt++) {
            const int ch0 = nt * 8 + 2 * tig;
            const float bc0 = cBias[64 + ch0], bc1 = cBias[64 + ch0 + 1];
#pragma unroll
            for (int hf = 0; hf < 2; hf++) {
                int px = wpx + mt * 16 + g + hf * 8;
                int wb = px * 36 + nt * 4 + tig;
                uint32_t hh = hs[wb], hl = hs[wb + 16];
                float h0 = bf_lo(hh) + bf_lo(hl);
                float h1 = bf_hi(hh) + bf_hi(hl);
                float c0 = tanhf_(dc[mt][nt][hf * 2 + 0] + bc0);
                float c1 = tanhf_(dc[mt][nt][hf * 2 + 1] + bc1);
                float t0 = fmaf(dz[mt][nt][hf * 2 + 0], c0 - h0, h0);
                float t1 = fmaf(dz[mt][nt][hf * 2 + 1], c1 - h1, h1);
                stg[px * 33 + ch0]     = t0;
                stg[px * 33 + ch0 + 1] = t1;
                uint32_t phi, plo;
                split2(t0, t1, phi, plo);
                ts[wb] = phi;  ts[wb + 16] = plo;
            }
        }
    __syncwarp();

    // coalesced h_t store (thread = own pixel row)
    {
        float* houtb = out + NB * 32 * HW + (b * 32) * HW + p0 + tid;
#pragma unroll
        for (int c2 = 0; c2 < 32; c2++) houtb[c2 * HW] = stg[tid * 33 + c2];
    }
    __syncwarp();

    // ---- phase 3: y = Wo * h_t + by ----
    float dy[2][4][4] = {};
    gemm_tile(dy, ts_a, 6, wf, lane, wpx);

#pragma unroll
    for (int mt = 0; mt < 2; mt++)
#pragma unroll
        for (int nt = 0; nt < 4; nt++) {
            const int ch0 = nt * 8 + 2 * tig;
            const float by0 = cBias[96 + ch0], by1 = cBias[96 + ch0 + 1];
#pragma unroll
            for (int hf = 0; hf < 2; hf++) {
                int px = wpx + mt * 16 + g + hf * 8;
                stg[px * 33 + ch0]     = dy[mt][nt][hf * 2 + 0] + by0;
                stg[px * 33 + ch0 + 1] = dy[mt][nt][hf * 2 + 1] + by1;
            }
        }
    __syncwarp();

    {
        float* youtb = out + (b * 32) * HW + p0 + tid;
#pragma unroll
        for (int c2 = 0; c2 < 32; c2++) youtb[c2 * HW] = stg[tid * 33 + c2];
    }
}

extern "C" void kernel_launch(void* const* d_in, const int* in_sizes, int n_in,
                              void* d_out, int out_size) {
    const float* x    = (const float*)d_in[0];
    const float* h    = (const float*)d_in[1];
    const float* w_xz = (const float*)d_in[2];
    const float* b_xz = (const float*)d_in[3];
    const float* w_hz = (const float*)d_in[4];
    const float* b_hz = (const float*)d_in[5];
    const float* w_xr = (const float*)d_in[6];
    const float* b_xr = (const float*)d_in[7];
    const float* w_hr = (const float*)d_in[8];
    const float* b_hr = (const float*)d_in[9];
    const float* w_c  = (const float*)d_in[10];
    const float* b_c  = (const float*)d_in[11];
    const float* w_u  = (const float*)d_in[12];
    const float* b_u  = (const float*)d_in[13];
    const float* w_o  = (const float*)d_in[14];
    const float* b_o  = (const float*)d_in[15];
    float* out = (float*)d_out;

    prep_kernel<<<7, 1024>>>(w_xz, w_hz, w_xr, w_hr, w_c, w_u, w_o,
                             b_xz, b_hz, b_xr, b_hr, b_c, b_u, b_o);

    void *csym = nullptr, *gsym = nullptr;
    cudaGetSymbolAddress(&csym, cBias);
    cudaGetSymbolAddress(&gsym, g_bias_stage);
    cudaMemcpyAsync(csym, gsym, sizeof(float) * 128, cudaMemcpyDeviceToDevice);

    cudaFuncSetAttribute(gru_mma_kernel,
                         cudaFuncAttributeMaxDynamicSharedMemorySize, SMEM_TOTAL);
    gru_mma_kernel<<<4096, 128, SMEM_TOTAL>>>(x, h, out);
}